// round 9
// baseline (speedup 1.0000x reference)
#include <cuda_runtime.h>
#include <math.h>

// ---------------------------------------------------------------------------
// Fully-fused KAN generator, one block per sample (512 blocks x 256 threads).
// R9: piecewise-quadratic reformulation. Per (parity,pos,c,co) the combined
// spline+relu response is a quadratic in the local knot coordinate t:
//     S(v) = alpha[slot] + t*beta[slot] + t^2*gamma[slot]
// slots: 0-6 knot intervals (3 = interval 3 with v<0), 7 = interval 3 with
// v>=0 (relu kink split), 8 = v>=7/3 (pure relu), 9 = v<-7/3 (zero).
// Features per source value: (t, t^2, slot_byte_offset) in ONE float4.
// Weight table: [p][pos][c][slot][{a,b,g}] float4-over-co, 30 KB in SMEM.
// Dynamic SMEM (55.5 KB) since static limit is 48 KB.
// ---------------------------------------------------------------------------

typedef unsigned long long ull;

__device__ __forceinline__ float ftanh(float x) {
    float e = __expf(2.0f * x);
    return 1.0f - __fdividef(2.0f, e + 1.0f);
}

// featurize: v -> (t, t^2, byte offset of slot)
__device__ __forceinline__ float4 featurize(float v) {
    float s  = fmaf(v, 1.5f, 3.5f);
    float kf = floorf(s);
    int   ki = (int)kf;
    int slot; float t;
    if (ki < 0)      { slot = 9; t = 0.0f; }
    else if (ki > 6) { slot = 8; t = v; }
    else             { slot = (ki == 3 && v >= 0.0f) ? 7 : ki; t = s - kf; }
    return make_float4(t, t * t, __int_as_float(slot * 48), 0.0f);
}

// border cell = value 0: slot 7, t = 0.5
#define F0 make_float4(0.5f, 0.25f, __int_as_float(7 * 48), 0.0f)

// ----------------------------- one conv stage ------------------------------
template <int HIN, int COUT, bool FINAL>
__device__ __forceinline__ void do_stage(
    const float* __restrict__ bw, const float* __restrict__ sw,
    float* act, float4* featA, float4* wsh4, float* gout)
{
    constexpr int S2   = HIN * HIN;
    constexpr int NSRC = 4 * S2;
    constexpr int HOUT = 2 * HIN;
    constexpr int HP   = HIN + 2;
    constexpr int S2P  = HP * HP;
    constexpr int NPX  = (S2 > 64) ? S2 / 64 : 1;
    constexpr int JSTR = (HIN >= 8) ? 64 / HIN : 1;
    const int tid = threadIdx.x;
    float* wshF = reinterpret_cast<float*>(wsh4);

    // --- build alpha/beta/gamma table: one (p,pos,c,co) combo per thread
    {
        int co  = tid & 3;
        int c   = (tid >> 2) & 3;
        int pos = (tid >> 4) & 3;
        int p   = tid >> 6;
        int py = p >> 1, px = p & 1;
        int ry = pos >> 1, rx = pos & 1;

        // tap-summed raw weights for this combo
        float w[5] = {0, 0, 0, 0, 0};
        float wb = 0.0f;
        if (co < COUT) {
            int ky0 = ry * (1 + py), nky = 1 + (ry ^ py);
            int kx0 = rx * (1 + px), nkx = 1 + (rx ^ px);
            for (int a = 0; a < nky; a++)
                for (int bb = 0; bb < nkx; bb++) {
                    int j = c * 9 + (ky0 + a) * 3 + (kx0 + bb);
                    wb += bw[co * 36 + j];
#pragma unroll
                    for (int f = 0; f < 5; f++)
                        w[f] += sw[(co * 36 + j) * 5 + f];
                }
        }

        // expand to 10 quadratic slots
        float* W = wshF + (((p * 4 + pos) * 4 + c) * 30) * 4 + co;
#pragma unroll
        for (int k = 0; k < 7; k++) {
            float w2 = (k >= 2) ? w[k - 2] : 0.0f;
            float w1 = (k >= 1 && k <= 5) ? w[k - 1] : 0.0f;
            float w0 = (k <= 4) ? w[k] : 0.0f;
            float A = 0.5f * (w2 + w1);
            float B = w1 - w2;
            float G = 0.5f * w2 - w1 + 0.5f * w0;
            if (k >= 4) {   // relu = v = (t + k - 3.5)/1.5 on v>0 intervals
                A = fmaf(((float)k - 3.5f) * (2.0f / 3.0f), wb, A);
                B = fmaf(2.0f / 3.0f, wb, B);
            }
            W[k * 12 + 0] = A; W[k * 12 + 4] = B; W[k * 12 + 8] = G;
        }
        {   // slot 7: interval 3 with v >= 0 (relu active)
            float w2 = w[1], w1 = w[2], w0 = w[3];
            float A = 0.5f * (w2 + w1) + (3.0f - 3.5f) * (2.0f / 3.0f) * wb;
            float B = (w1 - w2) + (2.0f / 3.0f) * wb;
            float G = 0.5f * w2 - w1 + 0.5f * w0;
            W[7 * 12 + 0] = A; W[7 * 12 + 4] = B; W[7 * 12 + 8] = G;
        }
        // slot 8: v >= 7/3 -> spline 0, relu = v (t stored = v)
        W[8 * 12 + 0] = 0.0f; W[8 * 12 + 4] = wb; W[8 * 12 + 8] = 0.0f;
        // slot 9: v < -7/3 -> zero
        W[9 * 12 + 0] = 0.0f; W[9 * 12 + 4] = 0.0f; W[9 * 12 + 8] = 0.0f;
    }

    // --- border ring: value-0 features
    {
        constexpr int NB = 2 * HP + 2 * HIN;
        for (int e = tid; e < 4 * NB; e += 256) {
            int c = e / NB, r = e % NB;
            int y, x;
            if (r < 2 * HP) { y = (r < HP) ? 0 : HP - 1; x = (r < HP) ? r : r - HP; }
            else { int r2 = r - 2 * HP;
                   y = 1 + ((r2 < HIN) ? r2 : r2 - HIN);
                   x = (r2 < HIN) ? 0 : HP - 1; }
            featA[c * S2P + y * HP + x] = F0;
        }
    }

    // --- featurize interior source values
#pragma unroll
    for (int k = 0; k < (NSRC + 255) / 256; k++) {
        int lv = tid + k * 256;
        if (NSRC >= 256 || lv < NSRC) {
            int c = lv / S2, rem = lv % S2;
            int y = rem / HIN, x = rem % HIN;
            featA[c * S2P + (y + 1) * HP + (x + 1)] = featurize(act[lv]);
        }
    }
    __syncthreads();

    // --- phase C
    const int p  = tid >> 6;       // warp-uniform parity
    const int l  = tid & 63;
    const int py = p >> 1, px = p & 1;

    if (S2 >= 64 || l < S2) {
        const int Yb = l / HIN;
        const int X  = l % HIN;
        const int base = (Yb + py) * HP + X + px;

        float4 acc[NPX];
#pragma unroll
        for (int j = 0; j < NPX; j++) acc[j] = make_float4(0.f, 0.f, 0.f, 0.f);

#pragma unroll
        for (int pos = 0; pos < 4; pos++) {
            const int ry = pos >> 1, rx = pos & 1;
#pragma unroll
            for (int c = 0; c < 4; c++) {
                const char* wpc = (const char*)(wsh4 + ((p * 4 + pos) * 4 + c) * 30);
                const int off = base + c * S2P + ry * HP + rx;
#pragma unroll
                for (int j = 0; j < NPX; j++) {
                    float4 ft = featA[off + j * JSTR * HP];
                    const float4* wv =
                        (const float4*)(wpc + __float_as_int(ft.z));
                    float4 A = wv[0], B = wv[1], G = wv[2];
                    acc[j].x += A.x;
                    acc[j].y += A.y;
                    acc[j].z += A.z;
                    if (COUT == 4) acc[j].w += A.w;
                    acc[j].x = fmaf(ft.x, B.x, acc[j].x);
                    acc[j].y = fmaf(ft.x, B.y, acc[j].y);
                    acc[j].z = fmaf(ft.x, B.z, acc[j].z);
                    if (COUT == 4) acc[j].w = fmaf(ft.x, B.w, acc[j].w);
                    acc[j].x = fmaf(ft.y, G.x, acc[j].x);
                    acc[j].y = fmaf(ft.y, G.y, acc[j].y);
                    acc[j].z = fmaf(ft.y, G.z, acc[j].z);
                    if (COUT == 4) acc[j].w = fmaf(ft.y, G.w, acc[j].w);
                }
            }
        }

        // --- write outputs
#pragma unroll
        for (int j = 0; j < NPX; j++) {
            int y = 2 * (Yb + j * JSTR) + py, x = 2 * X + px;
            if (FINAL) {
                gout[0 * HOUT * HOUT + y * HOUT + x] = ftanh(acc[j].x);
                gout[1 * HOUT * HOUT + y * HOUT + x] = ftanh(acc[j].y);
                gout[2 * HOUT * HOUT + y * HOUT + x] = ftanh(acc[j].z);
            } else {
                act[0 * HOUT * HOUT + y * HOUT + x] = acc[j].x;
                act[1 * HOUT * HOUT + y * HOUT + x] = acc[j].y;
                act[2 * HOUT * HOUT + y * HOUT + x] = acc[j].z;
                act[3 * HOUT * HOUT + y * HOUT + x] = acc[j].w;
            }
        }
    }
    __syncthreads();
}

// ----------------------------- fused kernel --------------------------------
// dynamic SMEM layout: act[1024] f32 | featA[4*18*18] f4 | wsh[1920] f4
static constexpr int SMEM_ACT   = 0;
static constexpr int SMEM_FEAT  = 4096;
static constexpr int SMEM_WSH   = 4096 + 4 * 18 * 18 * 16;   // 24832
static constexpr int SMEM_TOTAL = SMEM_WSH + 1920 * 16;      // 55552

__global__ void __launch_bounds__(256) fused_kan_kernel(
    const float* __restrict__ x,
    const float* __restrict__ lin_w,
    const float* __restrict__ lin_b,
    const float* __restrict__ bw1, const float* __restrict__ sw1,
    const float* __restrict__ bw2, const float* __restrict__ sw2,
    const float* __restrict__ bw3, const float* __restrict__ sw3,
    const float* __restrict__ bw4, const float* __restrict__ sw4,
    float* __restrict__ out)
{
    extern __shared__ char smem[];
    float*  act   = (float*)(smem + SMEM_ACT);
    float4* featA = (float4*)(smem + SMEM_FEAT);
    float4* wsh4  = (float4*)(smem + SMEM_WSH);

    const int tid = threadIdx.x;
    const int b   = blockIdx.x;

    // linear + relu: 16 outputs, 4 threads each over 25-element chunks
    if (tid < 64) {
        int j = tid >> 2, qp = tid & 3;
        const float* xr = x + b * 100 + qp * 25;
        const float* wr = lin_w + j * 100 + qp * 25;
        float acc = 0.0f;
#pragma unroll
        for (int i = 0; i < 25; i++) acc = fmaf(xr[i], wr[i], acc);
        acc += __shfl_xor_sync(0xffffffffu, acc, 1);
        acc += __shfl_xor_sync(0xffffffffu, acc, 2);
        if (qp == 0) act[j] = fmaxf(acc + lin_b[j], 0.0f);
    }
    __syncthreads();

    do_stage<2, 4, false>(bw1, sw1, act, featA, wsh4, nullptr);
    do_stage<4, 4, false>(bw2, sw2, act, featA, wsh4, nullptr);
    do_stage<8, 4, false>(bw3, sw3, act, featA, wsh4, nullptr);
    do_stage<16, 3, true>(bw4, sw4, act, featA, wsh4,
                          out + (size_t)b * 3 * 32 * 32);
}

// ---------------------------------------------------------------------------
extern "C" void kernel_launch(void* const* d_in, const int* in_sizes, int n_in,
                              void* d_out, int out_size) {
    const float* x     = (const float*)d_in[0];
    const float* lin_w = (const float*)d_in[1];
    const float* lin_b = (const float*)d_in[2];
    const float* bw1   = (const float*)d_in[3];
    const float* sw1   = (const float*)d_in[4];
    const float* bw2   = (const float*)d_in[5];
    const float* sw2   = (const float*)d_in[6];
    const float* bw3   = (const float*)d_in[7];
    const float* sw3   = (const float*)d_in[8];
    const float* bw4   = (const float*)d_in[9];
    const float* sw4   = (const float*)d_in[10];

    cudaFuncSetAttribute(fused_kan_kernel,
                         cudaFuncAttributeMaxDynamicSharedMemorySize,
                         SMEM_TOTAL);
    fused_kan_kernel<<<512, 256, SMEM_TOTAL>>>(
        x, lin_w, lin_b, bw1, sw1, bw2, sw2, bw3, sw3, bw4, sw4,
        (float*)d_out);
}